// round 5
// baseline (speedup 1.0000x reference)
#include <cuda_runtime.h>
#include <cuda_bf16.h>
#include <cstdint>

#define NROWS 8192
#define DIM   512
#define SCALE 2.659f

__device__ __nv_bfloat16 g_img[NROWS * DIM];
__device__ __nv_bfloat16 g_txt[NROWS * DIM];
__device__ int   g_key[NROWS];
__device__ float g_cnt[NROWS];
__device__ float g_rowsum[NROWS];
__device__ float g_rowdot[NROWS];
__device__ float g_colsum[NROWS];
__device__ float g_coldot[NROWS];
__device__ int   g_done;

// ---------------- asm helpers ----------------
#define MMA_BF16(C, A, B0, B1)                                               \
    asm volatile(                                                            \
        "mma.sync.aligned.m16n8k16.row.col.f32.bf16.bf16.f32 "               \
        "{%0,%1,%2,%3}, {%4,%5,%6,%7}, {%8,%9}, {%0,%1,%2,%3};"              \
        : "+f"((C)[0]), "+f"((C)[1]), "+f"((C)[2]), "+f"((C)[3])             \
        : "r"((A)[0]), "r"((A)[1]), "r"((A)[2]), "r"((A)[3]),                \
          "r"(B0), "r"(B1))

#define LDSM4(R, ADDR)                                                       \
    asm volatile("ldmatrix.sync.aligned.m8n8.x4.shared.b16 {%0,%1,%2,%3}, [%4];" \
                 : "=r"((R)[0]), "=r"((R)[1]), "=r"((R)[2]), "=r"((R)[3])    \
                 : "r"(ADDR))

#define CP_ASYNC16(dst, src)                                                 \
    asm volatile("cp.async.cg.shared.global [%0], [%1], 16;"                 \
                 :: "r"(dst), "l"(src))
#define CP_COMMIT() asm volatile("cp.async.commit_group;" ::: "memory")
#define CP_WAIT(N)  asm volatile("cp.async.wait_group %0;" :: "n"(N) : "memory")

// ---------------------------------------------------------------------------
// Prep kernel: grid (NROWS+1, 2), 128 threads.
//   blockIdx.x < NROWS  -> L2-normalize one row (y=0 image, y=1 text).
//   blockIdx.x == NROWS, y == 0 -> label prep: dtype sniff (int64 vs int32),
//   canonical keys, histogram counts, zero global accumulators + done flag.
// ---------------------------------------------------------------------------
__global__ void prep_kernel(const float* __restrict__ text,
                            const float* __restrict__ image,
                            const int* __restrict__ p) {
    int tid = threadIdx.x;
    if (blockIdx.x == NROWS) {
        if (blockIdx.y != 0) return;
        __shared__ int viol;
        __shared__ int h[128];
        if (tid == 0) { viol = 0; g_done = 0; }
        h[tid] = 0;
        __syncthreads();
        int v = 0;
        for (int i = tid; i < NROWS / 2; i += 128) {
            int hiw = p[2 * i + 1];
            if (hiw != 0 && hiw != -1) v = 1;
        }
        if (v) atomicAdd(&viol, 1);
        __syncthreads();
        bool is64 = (viol == 0);
        for (int i = tid; i < NROWS; i += 128) {
            int l = is64 ? p[2 * i] : p[i];
            g_key[i] = (l >= 0 && l < 128) ? l : (1 << 20) + i;
            if (l >= 0 && l < 128) atomicAdd(&h[l], 1);
            g_rowsum[i] = 0.0f; g_rowdot[i] = 0.0f;
            g_colsum[i] = 0.0f; g_coldot[i] = 0.0f;
        }
        __syncthreads();
        for (int i = tid; i < NROWS; i += 128) {
            int k = g_key[i];
            g_cnt[i] = (k < 128) ? (float)h[k] : 1.0f;
        }
        return;
    }

    int row = blockIdx.x;
    const float* src = blockIdx.y ? text : image;
    __nv_bfloat16* dst = blockIdx.y ? g_txt : g_img;
    int lane = tid & 31, wid = tid >> 5;

    float4 v = ((const float4*)(src + (size_t)row * DIM))[tid];
    float ss = v.x * v.x + v.y * v.y + v.z * v.z + v.w * v.w;
#pragma unroll
    for (int o = 16; o; o >>= 1) ss += __shfl_xor_sync(0xffffffffu, ss, o);
    __shared__ float wss[4];
    if (lane == 0) wss[wid] = ss;
    __syncthreads();
    float tot = wss[0] + wss[1] + wss[2] + wss[3];
    float inv = 1.0f / fmaxf(sqrtf(tot), 1e-12f);

    __nv_bfloat162* dp = (__nv_bfloat162*)(dst + (size_t)row * DIM);
    dp[2 * tid]     = __floats2bfloat162_rn(v.x * inv, v.y * inv);
    dp[2 * tid + 1] = __floats2bfloat162_rn(v.z * inv, v.w * inv);
}

// ---------------------------------------------------------------------------
// Main kernel: single pass over S = img_n @ txt_n^T, 64x64 warp tiles.
// grid (64, 16): x = 128-row m-block, y = 512-col n-group (2 halves of 256).
// A panel (128x512) resident in smem; B streamed via 2-stage ring (32KB each,
// stage = [256 cols][64 k]). 8 warps = 2m x 4n. Last CTA computes the loss.
// ---------------------------------------------------------------------------
__global__ __launch_bounds__(256, 1)
void unicl_gemm_kernel(float* __restrict__ out) {
    extern __shared__ char sm[];
    uint32_t sbase = (uint32_t)__cvta_generic_to_shared(sm);
    const uint32_t As_u = sbase;               // [8 k-chunks][128 rows][64 k]
    const uint32_t Bs_u = sbase + 131072u;     // 2 stages x [256][64]
    int*   keys_s = (int*)(sm + 196608);       // 512
    float* row_se = (float*)(sm + 198656);     // 128
    float* row_dt = row_se + 128;              // 128
    float* col_se = (float*)(sm + 199680);     // 512
    float* col_dt = col_se + 512;              // 512
    int*   flag_s = (int*)(sm + 203776);
    float* red_s  = (float*)(sm + 203776);     // reused for final reduce (256)

    int tid = threadIdx.x, lane = tid & 31, wid = tid >> 5;
    int gm0 = blockIdx.x * 128;
    int n0  = blockIdx.y * 512;
    const __nv_bfloat16* Ag = g_img;
    const __nv_bfloat16* Bg = g_txt;

    for (int i = tid; i < 128; i += 256) { row_se[i] = 0.0f; row_dt[i] = 0.0f; }
    for (int i = tid; i < 512; i += 256) {
        col_se[i] = 0.0f; col_dt[i] = 0.0f;
        keys_s[i] = g_key[n0 + i];
    }

    // --- A prologue: 128x512 bf16 into [s8][128][64] swizzled ---
#pragma unroll
    for (int q = 0; q < 32; q++) {
        int idx = tid + q * 256;
        int s8 = idx >> 10, row = (idx >> 3) & 127, ch = idx & 7;
        const void* src = Ag + (size_t)(gm0 + row) * DIM + s8 * 64 + ch * 8;
        uint32_t dst = As_u + s8 * 16384 + row * 128 + ((ch ^ (row & 7)) << 4);
        CP_ASYNC16(dst, src);
    }
    CP_COMMIT();

    auto issueB = [&](int gs) {
        int t = gs >> 3, s8 = gs & 7;
        const __nv_bfloat16* bsrc = Bg + (size_t)(n0 + t * 256) * DIM + s8 * 64;
        uint32_t bdst = Bs_u + (uint32_t)(gs & 1) * 32768u;
#pragma unroll
        for (int q = 0; q < 8; q++) {
            int idx = tid + q * 256;
            int row = idx >> 3, ch = idx & 7;
            CP_ASYNC16(bdst + row * 128 + ((ch ^ (row & 7)) << 4),
                       bsrc + (size_t)row * DIM + ch * 8);
        }
    };
    issueB(0); CP_COMMIT();
    issueB(1); CP_COMMIT();

    // --- warp geometry: 2 m-warps (64 rows) x 4 n-warps (64 cols) ---
    int warp_m = (wid & 1) * 64;
    int warp_n = (wid >> 1) * 64;
    int g = lane >> 2, tig = lane & 3;
    uint32_t a_off = (uint32_t)(warp_m + (lane & 15)) * 128;
    uint32_t hiA = (uint32_t)(lane >> 4);
    uint32_t swA = (uint32_t)(lane & 7);
    int rB0 = warp_n + (lane & 7) + ((lane >> 4) << 3);
    uint32_t b_off = (uint32_t)rB0 * 128;
    uint32_t hiB = (uint32_t)((lane >> 3) & 1);
    uint32_t swB = (uint32_t)(lane & 7);

    int mykey[8];
#pragma unroll
    for (int ri = 0; ri < 8; ri++)
        mykey[ri] = g_key[gm0 + warp_m + (ri >> 1) * 16 + (ri & 1) * 8 + g];

    float rse[8], rdt[8];
#pragma unroll
    for (int i = 0; i < 8; i++) { rse[i] = 0.0f; rdt[i] = 0.0f; }
    const float K2 = SCALE * 1.44269504f;

    for (int t = 0; t < 2; t++) {
        float c[4][8][4];
#pragma unroll
        for (int mf = 0; mf < 4; mf++)
#pragma unroll
            for (int nf = 0; nf < 8; nf++)
#pragma unroll
                for (int e = 0; e < 4; e++) c[mf][nf][e] = 0.0f;

#pragma unroll 1
        for (int s8 = 0; s8 < 8; s8++) {
            int gs = t * 8 + s8;
            if (gs < 15) { CP_WAIT(1); } else { CP_WAIT(0); }
            __syncthreads();

            uint32_t Ab = As_u + s8 * 16384;
            uint32_t Bb = Bs_u + (uint32_t)(gs & 1) * 32768u;
#pragma unroll
            for (int k16 = 0; k16 < 4; k16++) {
                uint32_t a[4][4], b[4][4];
                uint32_t cA = ((k16 * 2 + hiA) ^ swA) << 4;
                LDSM4(a[0], Ab + a_off + cA);
                LDSM4(a[1], Ab + a_off + 2048 + cA);
                LDSM4(a[2], Ab + a_off + 4096 + cA);
                LDSM4(a[3], Ab + a_off + 6144 + cA);
                uint32_t cB = ((k16 * 2 + hiB) ^ swB) << 4;
                LDSM4(b[0], Bb + b_off + cB);
                LDSM4(b[1], Bb + b_off + 2048 + cB);
                LDSM4(b[2], Bb + b_off + 4096 + cB);
                LDSM4(b[3], Bb + b_off + 6144 + cB);
#pragma unroll
                for (int mf = 0; mf < 4; mf++) {
#pragma unroll
                    for (int j = 0; j < 4; j++) {
                        MMA_BF16(c[mf][2 * j],     a[mf], b[j][0], b[j][1]);
                        MMA_BF16(c[mf][2 * j + 1], a[mf], b[j][2], b[j][3]);
                    }
                }
            }
            __syncthreads();
            if (gs + 2 < 16) { issueB(gs + 2); CP_COMMIT(); }
        }

        // --- epilogue for n-half t (overlaps next half's loads) ---
        float cse[16], cdt[16];
#pragma unroll
        for (int p = 0; p < 16; p++) { cse[p] = 0.0f; cdt[p] = 0.0f; }
        const int* ks = keys_s + t * 256 + warp_n;
#pragma unroll
        for (int mf = 0; mf < 4; mf++) {
#pragma unroll
            for (int nf = 0; nf < 8; nf++) {
#pragma unroll
                for (int e = 0; e < 4; e++) {
                    float cv = c[mf][nf][e];
                    float ex;
                    asm("ex2.approx.ftz.f32 %0, %1;" : "=f"(ex)
                        : "f"(fmaf(cv, K2, -K2)));
                    int ri = mf * 2 + (e >> 1);
                    int p  = nf * 2 + (e & 1);
                    rse[ri] += ex;
                    cse[p]  += ex;
                    int key = ks[nf * 8 + tig * 2 + (e & 1)];
                    if (key == mykey[ri]) { rdt[ri] += cv; cdt[p] += cv; }
                }
            }
        }
#pragma unroll
        for (int p = 0; p < 16; p++) {
            cse[p] += __shfl_xor_sync(0xffffffffu, cse[p], 4);
            cse[p] += __shfl_xor_sync(0xffffffffu, cse[p], 8);
            cse[p] += __shfl_xor_sync(0xffffffffu, cse[p], 16);
            cdt[p] += __shfl_xor_sync(0xffffffffu, cdt[p], 4);
            cdt[p] += __shfl_xor_sync(0xffffffffu, cdt[p], 8);
            cdt[p] += __shfl_xor_sync(0xffffffffu, cdt[p], 16);
        }
#pragma unroll
        for (int q = 0; q < 2; q++) {
            int p = g * 2 + q;
            int cidx = t * 256 + warp_n + (p >> 1) * 8 + tig * 2 + (p & 1);
            atomicAdd(&col_se[cidx], cse[p]);
            atomicAdd(&col_dt[cidx], cdt[p]);
        }
    }

    // --- row reduction + CTA flush ---
#pragma unroll
    for (int ri = 0; ri < 8; ri++) {
        float v = rse[ri];
        v += __shfl_xor_sync(0xffffffffu, v, 1);
        v += __shfl_xor_sync(0xffffffffu, v, 2);
        float w = rdt[ri];
        w += __shfl_xor_sync(0xffffffffu, w, 1);
        w += __shfl_xor_sync(0xffffffffu, w, 2);
        if (tig == 0) {
            int rl = warp_m + (ri >> 1) * 16 + (ri & 1) * 8 + g;
            atomicAdd(&row_se[rl], v);
            atomicAdd(&row_dt[rl], w);
        }
    }
    __syncthreads();
    for (int i = tid; i < 128; i += 256) {
        atomicAdd(&g_rowsum[gm0 + i], row_se[i]);
        atomicAdd(&g_rowdot[gm0 + i], row_dt[i]);
    }
    for (int i = tid; i < 512; i += 256) {
        atomicAdd(&g_colsum[n0 + i], col_se[i]);
        atomicAdd(&g_coldot[n0 + i], col_dt[i]);
    }

    // --- last CTA computes the final loss ---
    __threadfence();
    __syncthreads();
    if (tid == 0) {
        int prev = atomicAdd(&g_done, 1);
        flag_s[0] = (prev == gridDim.x * gridDim.y - 1) ? 1 : 0;
    }
    __syncthreads();
    if (flag_s[0]) {
        __threadfence();
        float s = 0.0f;
        for (int i = tid; i < NROWS; i += 256) {
            float inv = SCALE / g_cnt[i];
            s += 2.0f * SCALE + logf(g_rowsum[i]) + logf(g_colsum[i])
                 - (g_rowdot[i] + g_coldot[i]) * inv;
        }
        __syncthreads();
        red_s[tid] = s;
        __syncthreads();
        for (int o = 128; o; o >>= 1) {
            if (tid < o) red_s[tid] += red_s[tid + o];
            __syncthreads();
        }
        if (tid == 0) out[0] = red_s[0] * (1.0f / (2.0f * NROWS));
    }
}

// ---------------------------------------------------------------------------
extern "C" void kernel_launch(void* const* d_in, const int* in_sizes, int n_in,
                              void* d_out, int out_size) {
    const float* text   = (const float*)d_in[0];
    const float* image  = (const float*)d_in[1];
    const int*   labels = (const int*)d_in[2];
    float* out = (float*)d_out;

    prep_kernel<<<dim3(NROWS + 1, 2), 128>>>(text, image, labels);

    int smem_bytes = 204800;
    cudaFuncSetAttribute(unicl_gemm_kernel,
                         cudaFuncAttributeMaxDynamicSharedMemorySize, smem_bytes);
    unicl_gemm_kernel<<<dim3(64, 16), 256, smem_bytes>>>(out);
}

// round 6
// speedup vs baseline: 1.4826x; 1.4826x over previous
#include <cuda_runtime.h>
#include <cuda_bf16.h>
#include <cstdint>

#define NROWS 8192
#define DIM   512
#define SCALE 2.659f

__device__ __nv_bfloat16 g_img[NROWS * DIM];
__device__ __nv_bfloat16 g_txt[NROWS * DIM];
__device__ int   g_key[NROWS];
__device__ float g_cnt[NROWS];
__device__ float g_rowsum[NROWS];
__device__ float g_rowdot[NROWS];
__device__ float g_colsum[NROWS];
__device__ float g_coldot[NROWS];
__device__ int   g_done;

// ---------------- asm helpers ----------------
#define MMA_BF16(C, A, B0, B1)                                               \
    asm volatile(                                                            \
        "mma.sync.aligned.m16n8k16.row.col.f32.bf16.bf16.f32 "               \
        "{%0,%1,%2,%3}, {%4,%5,%6,%7}, {%8,%9}, {%0,%1,%2,%3};"              \
        : "+f"((C)[0]), "+f"((C)[1]), "+f"((C)[2]), "+f"((C)[3])             \
        : "r"((A)[0]), "r"((A)[1]), "r"((A)[2]), "r"((A)[3]),                \
          "r"(B0), "r"(B1))

#define LDSM4(R, ADDR)                                                       \
    asm volatile("ldmatrix.sync.aligned.m8n8.x4.shared.b16 {%0,%1,%2,%3}, [%4];" \
                 : "=r"((R)[0]), "=r"((R)[1]), "=r"((R)[2]), "=r"((R)[3])    \
                 : "r"(ADDR))

#define CP_ASYNC16(dst, src)                                                 \
    asm volatile("cp.async.cg.shared.global [%0], [%1], 16;"                 \
                 :: "r"(dst), "l"(src))
#define CP_COMMIT() asm volatile("cp.async.commit_group;" ::: "memory")
#define CP_WAIT(N)  asm volatile("cp.async.wait_group %0;" :: "n"(N) : "memory")

// ---------------------------------------------------------------------------
// Prep kernel: grid (NROWS+1, 2), 128 threads.
//   blockIdx.x < NROWS  -> L2-normalize one row (y=0 image, y=1 text).
//   blockIdx.x == NROWS, y == 0 -> label prep (dtype sniff, keys, counts,
//   zero accumulators).
// ---------------------------------------------------------------------------
__global__ void prep_kernel(const float* __restrict__ text,
                            const float* __restrict__ image,
                            const int* __restrict__ p) {
    int tid = threadIdx.x;
    if (blockIdx.x == NROWS) {
        if (blockIdx.y != 0) return;
        __shared__ int viol;
        __shared__ int h[128];
        if (tid == 0) { viol = 0; g_done = 0; }
        h[tid] = 0;
        __syncthreads();
        int v = 0;
        for (int i = tid; i < NROWS / 2; i += 128) {
            int hiw = p[2 * i + 1];
            if (hiw != 0 && hiw != -1) v = 1;
        }
        if (v) atomicAdd(&viol, 1);
        __syncthreads();
        bool is64 = (viol == 0);
        for (int i = tid; i < NROWS; i += 128) {
            int l = is64 ? p[2 * i] : p[i];
            g_key[i] = (l >= 0 && l < 128) ? l : (1 << 20) + i;
            if (l >= 0 && l < 128) atomicAdd(&h[l], 1);
            g_rowsum[i] = 0.0f; g_rowdot[i] = 0.0f;
            g_colsum[i] = 0.0f; g_coldot[i] = 0.0f;
        }
        __syncthreads();
        for (int i = tid; i < NROWS; i += 128) {
            int k = g_key[i];
            g_cnt[i] = (k < 128) ? (float)h[k] : 1.0f;
        }
        return;
    }

    int row = blockIdx.x;
    const float* src = blockIdx.y ? text : image;
    __nv_bfloat16* dst = blockIdx.y ? g_txt : g_img;
    int lane = tid & 31, wid = tid >> 5;

    float4 v = ((const float4*)(src + (size_t)row * DIM))[tid];
    float ss = v.x * v.x + v.y * v.y + v.z * v.z + v.w * v.w;
#pragma unroll
    for (int o = 16; o; o >>= 1) ss += __shfl_xor_sync(0xffffffffu, ss, o);
    __shared__ float wss[4];
    if (lane == 0) wss[wid] = ss;
    __syncthreads();
    float tot = wss[0] + wss[1] + wss[2] + wss[3];
    float inv = 1.0f / fmaxf(sqrtf(tot), 1e-12f);

    __nv_bfloat162* dp = (__nv_bfloat162*)(dst + (size_t)row * DIM);
    dp[2 * tid]     = __floats2bfloat162_rn(v.x * inv, v.y * inv);
    dp[2 * tid + 1] = __floats2bfloat162_rn(v.z * inv, v.w * inv);
}

// ---------------------------------------------------------------------------
// Main kernel: single pass over S = img_n @ txt_n^T.
// grid (64, 16), 512 threads (16 warps = 4m x 4n), warp tile 32x64.
// x = 128-row m-block, y = 512-col n-group processed as 2 halves of 256.
// A panel (128x512) resident in smem; B 2-stage cp.async ring (32KB/stage).
// Row and column softmax stats accumulated per CTA, flushed by atomics;
// last CTA computes the final scalar loss.
// ---------------------------------------------------------------------------
__global__ __launch_bounds__(512, 1)
void unicl_gemm_kernel(float* __restrict__ out) {
    extern __shared__ char sm[];
    uint32_t sbase = (uint32_t)__cvta_generic_to_shared(sm);
    const uint32_t As_u = sbase;               // [8 k-chunks][128 rows][64 k]
    const uint32_t Bs_u = sbase + 131072u;     // 2 stages x [256 cols][64 k]
    int*   keys_s = (int*)(sm + 196608);       // 512
    float* row_se = (float*)(sm + 198656);     // 128
    float* row_dt = row_se + 128;              // 128
    float* col_se = (float*)(sm + 199680);     // 512
    float* col_dt = col_se + 512;              // 512
    int*   flag_s = (int*)(sm + 203776);
    float* red_s  = (float*)(sm + 203776);     // reused for final reduce (512)

    int tid = threadIdx.x, lane = tid & 31, wid = tid >> 5;
    int gm0 = blockIdx.x * 128;
    int n0  = blockIdx.y * 512;
    const __nv_bfloat16* Ag = g_img;
    const __nv_bfloat16* Bg = g_txt;

    for (int i = tid; i < 128; i += 512) { row_se[i] = 0.0f; row_dt[i] = 0.0f; }
    for (int i = tid; i < 512; i += 512) {
        col_se[i] = 0.0f; col_dt[i] = 0.0f;
        keys_s[i] = g_key[n0 + i];
    }

    // --- A prologue: 128x512 bf16 into [s8][128][64] swizzled ---
#pragma unroll
    for (int q = 0; q < 16; q++) {
        int idx = tid + q * 512;
        int s8 = idx >> 10, row = (idx >> 3) & 127, ch = idx & 7;
        const void* src = Ag + (size_t)(gm0 + row) * DIM + s8 * 64 + ch * 8;
        uint32_t dst = As_u + s8 * 16384 + row * 128 + ((ch ^ (row & 7)) << 4);
        CP_ASYNC16(dst, src);
    }
    CP_COMMIT();

    auto issueB = [&](int gs) {
        int t = gs >> 3, s8 = gs & 7;
        const __nv_bfloat16* bsrc = Bg + (size_t)(n0 + t * 256) * DIM + s8 * 64;
        uint32_t bdst = Bs_u + (uint32_t)(gs & 1) * 32768u;
#pragma unroll
        for (int q = 0; q < 4; q++) {
            int idx = tid + q * 512;
            int row = idx >> 3, ch = idx & 7;
            CP_ASYNC16(bdst + row * 128 + ((ch ^ (row & 7)) << 4),
                       bsrc + (size_t)row * DIM + ch * 8);
        }
    };
    issueB(0); CP_COMMIT();
    issueB(1); CP_COMMIT();

    // --- warp geometry: 4 m-warps (32 rows) x 4 n-warps (64 cols) ---
    int warp_m = (wid & 3) * 32;
    int warp_n = (wid >> 2) * 64;
    int g = lane >> 2, tig = lane & 3;
    uint32_t a_off = (uint32_t)(warp_m + (lane & 15)) * 128;
    uint32_t hiA = (uint32_t)(lane >> 4);
    uint32_t swA = (uint32_t)(lane & 7);
    int rB0 = warp_n + (lane & 7) + ((lane >> 4) << 3);
    uint32_t b_off = (uint32_t)rB0 * 128;
    uint32_t hiB = (uint32_t)((lane >> 3) & 1);
    uint32_t swB = (uint32_t)(lane & 7);

    int mykey[4];
#pragma unroll
    for (int ri = 0; ri < 4; ri++)
        mykey[ri] = g_key[gm0 + warp_m + g + ri * 8];

    float rse[4] = {0.f, 0.f, 0.f, 0.f};
    float rdt[4] = {0.f, 0.f, 0.f, 0.f};
    const float K2 = SCALE * 1.44269504f;

    for (int t = 0; t < 2; t++) {
        float c[2][8][4];
#pragma unroll
        for (int mf = 0; mf < 2; mf++)
#pragma unroll
            for (int nf = 0; nf < 8; nf++)
#pragma unroll
                for (int e = 0; e < 4; e++) c[mf][nf][e] = 0.0f;

#pragma unroll 1
        for (int s8 = 0; s8 < 8; s8++) {
            int gs = t * 8 + s8;
            if (gs < 15) { CP_WAIT(1); } else { CP_WAIT(0); }
            __syncthreads();

            uint32_t Ab = As_u + s8 * 16384;
            uint32_t Bb = Bs_u + (uint32_t)(gs & 1) * 32768u;
#pragma unroll
            for (int k16 = 0; k16 < 4; k16++) {
                uint32_t a0[4], a1[4], b[4][4];
                uint32_t cA = ((k16 * 2 + hiA) ^ swA) << 4;
                LDSM4(a0, Ab + a_off + cA);
                LDSM4(a1, Ab + a_off + 2048 + cA);
                uint32_t cB = ((k16 * 2 + hiB) ^ swB) << 4;
                LDSM4(b[0], Bb + b_off + cB);
                LDSM4(b[1], Bb + b_off + 2048 + cB);
                LDSM4(b[2], Bb + b_off + 4096 + cB);
                LDSM4(b[3], Bb + b_off + 6144 + cB);
#pragma unroll
                for (int j = 0; j < 4; j++) {
                    MMA_BF16(c[0][2 * j],     a0, b[j][0], b[j][1]);
                    MMA_BF16(c[0][2 * j + 1], a0, b[j][2], b[j][3]);
                    MMA_BF16(c[1][2 * j],     a1, b[j][0], b[j][1]);
                    MMA_BF16(c[1][2 * j + 1], a1, b[j][2], b[j][3]);
                }
            }
            __syncthreads();
            if (gs + 2 < 16) { issueB(gs + 2); CP_COMMIT(); }
        }

        // --- epilogue for n-half t (overlaps next half's B loads) ---
        float cse[16], cdt[16];
#pragma unroll
        for (int p = 0; p < 16; p++) { cse[p] = 0.0f; cdt[p] = 0.0f; }
        const int* ks = keys_s + t * 256 + warp_n;
#pragma unroll
        for (int mf = 0; mf < 2; mf++) {
#pragma unroll
            for (int nf = 0; nf < 8; nf++) {
#pragma unroll
                for (int e = 0; e < 4; e++) {
                    float cv = c[mf][nf][e];
                    float ex;
                    asm("ex2.approx.ftz.f32 %0, %1;" : "=f"(ex)
                        : "f"(fmaf(cv, K2, -K2)));
                    int ri = mf * 2 + (e >> 1);
                    int p  = nf * 2 + (e & 1);
                    rse[ri] += ex;
                    cse[p]  += ex;
                    int key = ks[nf * 8 + tig * 2 + (e & 1)];
                    if (key == mykey[ri]) { rdt[ri] += cv; cdt[p] += cv; }
                }
            }
        }
#pragma unroll
        for (int p = 0; p < 16; p++) {
            cse[p] += __shfl_xor_sync(0xffffffffu, cse[p], 4);
            cse[p] += __shfl_xor_sync(0xffffffffu, cse[p], 8);
            cse[p] += __shfl_xor_sync(0xffffffffu, cse[p], 16);
            cdt[p] += __shfl_xor_sync(0xffffffffu, cdt[p], 4);
            cdt[p] += __shfl_xor_sync(0xffffffffu, cdt[p], 8);
            cdt[p] += __shfl_xor_sync(0xffffffffu, cdt[p], 16);
        }
#pragma unroll
        for (int q = 0; q < 2; q++) {
            int p = g * 2 + q;
            int cidx = t * 256 + warp_n + (p >> 1) * 8 + tig * 2 + (p & 1);
            atomicAdd(&col_se[cidx], cse[p]);
            atomicAdd(&col_dt[cidx], cdt[p]);
        }
    }

    // --- row reduction + CTA flush ---
#pragma unroll
    for (int ri = 0; ri < 4; ri++) {
        float v = rse[ri];
        v += __shfl_xor_sync(0xffffffffu, v, 1);
        v += __shfl_xor_sync(0xffffffffu, v, 2);
        float w = rdt[ri];
        w += __shfl_xor_sync(0xffffffffu, w, 1);
        w += __shfl_xor_sync(0xffffffffu, w, 2);
        if (tig == 0) {
            atomicAdd(&row_se[warp_m + g + ri * 8], v);
            atomicAdd(&row_dt[warp_m + g + ri * 8], w);
        }
    }
    __syncthreads();
    for (int i = tid; i < 128; i += 512) {
        atomicAdd(&g_rowsum[gm0 + i], row_se[i]);
        atomicAdd(&g_rowdot[gm0 + i], row_dt[i]);
    }
    for (int i = tid; i < 512; i += 512) {
        atomicAdd(&g_colsum[n0 + i], col_se[i]);
        atomicAdd(&g_coldot[n0 + i], col_dt[i]);
    }

    // --- last CTA computes the final loss ---
    __threadfence();
    __syncthreads();
    if (tid == 0) {
        int prev = atomicAdd(&g_done, 1);
        flag_s[0] = (prev == gridDim.x * gridDim.y - 1) ? 1 : 0;
    }
    __syncthreads();
    if (flag_s[0]) {
        __threadfence();
        float s = 0.0f;
        for (int i = tid; i < NROWS; i += 512) {
            float inv = SCALE / g_cnt[i];
            s += 2.0f * SCALE + logf(g_rowsum[i]) + logf(g_colsum[i])
                 - (g_rowdot[i] + g_coldot[i]) * inv;
        }
        __syncthreads();
        red_s[tid] = s;
        __syncthreads();
        for (int o = 256; o; o >>= 1) {
            if (tid < o) red_s[tid] += red_s[tid + o];
            __syncthreads();
        }
        if (tid == 0) out[0] = red_s[0] * (1.0f / (2.0f * NROWS));
    }
}

// ---------------------------------------------------------------------------
extern "C" void kernel_launch(void* const* d_in, const int* in_sizes, int n_in,
                              void* d_out, int out_size) {
    const float* text   = (const float*)d_in[0];
    const float* image  = (const float*)d_in[1];
    const int*   labels = (const int*)d_in[2];
    float* out = (float*)d_out;

    prep_kernel<<<dim3(NROWS + 1, 2), 128>>>(text, image, labels);

    int smem_bytes = 205824;
    cudaFuncSetAttribute(unicl_gemm_kernel,
                         cudaFuncAttributeMaxDynamicSharedMemorySize, smem_bytes);
    unicl_gemm_kernel<<<dim3(64, 16), 512, smem_bytes>>>(out);
}

// round 7
// speedup vs baseline: 1.5730x; 1.0609x over previous
#include <cuda_runtime.h>
#include <cuda_bf16.h>
#include <cstdint>

#define NROWS 8192
#define DIM   512
#define SCALE 2.659f

__device__ __nv_bfloat16 g_img[NROWS * DIM];
__device__ __nv_bfloat16 g_txt[NROWS * DIM];
__device__ int   g_key[NROWS];
__device__ float g_cnt[NROWS];
__device__ float g_rowsum[NROWS];
__device__ float g_rowdot[NROWS];
__device__ float g_colsum[NROWS];
__device__ float g_coldot[NROWS];
__device__ int   g_done;

// ---------------- asm helpers ----------------
#define MMA_BF16(C, A, B0, B1)                                               \
    asm volatile(                                                            \
        "mma.sync.aligned.m16n8k16.row.col.f32.bf16.bf16.f32 "               \
        "{%0,%1,%2,%3}, {%4,%5,%6,%7}, {%8,%9}, {%0,%1,%2,%3};"              \
        : "+f"((C)[0]), "+f"((C)[1]), "+f"((C)[2]), "+f"((C)[3])             \
        : "r"((A)[0]), "r"((A)[1]), "r"((A)[2]), "r"((A)[3]),                \
          "r"(B0), "r"(B1))

#define LDSM4(R, ADDR)                                                       \
    asm volatile("ldmatrix.sync.aligned.m8n8.x4.shared.b16 {%0,%1,%2,%3}, [%4];" \
                 : "=r"((R)[0]), "=r"((R)[1]), "=r"((R)[2]), "=r"((R)[3])    \
                 : "r"(ADDR))

#define CP_ASYNC16(dst, src)                                                 \
    asm volatile("cp.async.cg.shared.global [%0], [%1], 16;"                 \
                 :: "r"(dst), "l"(src))
#define CP_COMMIT() asm volatile("cp.async.commit_group;" ::: "memory")
#define CP_WAIT(N)  asm volatile("cp.async.wait_group %0;" :: "n"(N) : "memory")

// ---------------------------------------------------------------------------
// Prep kernel: grid (NROWS+1, 2), 128 threads.
//   blockIdx.x < NROWS  -> L2-normalize one row (y=0 image, y=1 text).
//   blockIdx.x == NROWS, y == 0 -> label prep (dtype sniff, keys, counts,
//   zero accumulators).
// ---------------------------------------------------------------------------
__global__ void prep_kernel(const float* __restrict__ text,
                            const float* __restrict__ image,
                            const int* __restrict__ p) {
    int tid = threadIdx.x;
    if (blockIdx.x == NROWS) {
        if (blockIdx.y != 0) return;
        __shared__ int viol;
        __shared__ int h[128];
        if (tid == 0) { viol = 0; g_done = 0; }
        h[tid] = 0;
        __syncthreads();
        int v = 0;
        for (int i = tid; i < NROWS / 2; i += 128) {
            int hiw = p[2 * i + 1];
            if (hiw != 0 && hiw != -1) v = 1;
        }
        if (v) atomicAdd(&viol, 1);
        __syncthreads();
        bool is64 = (viol == 0);
        for (int i = tid; i < NROWS; i += 128) {
            int l = is64 ? p[2 * i] : p[i];
            g_key[i] = (l >= 0 && l < 128) ? l : (1 << 20) + i;
            if (l >= 0 && l < 128) atomicAdd(&h[l], 1);
            g_rowsum[i] = 0.0f; g_rowdot[i] = 0.0f;
            g_colsum[i] = 0.0f; g_coldot[i] = 0.0f;
        }
        __syncthreads();
        for (int i = tid; i < NROWS; i += 128) {
            int k = g_key[i];
            g_cnt[i] = (k < 128) ? (float)h[k] : 1.0f;
        }
        return;
    }

    int row = blockIdx.x;
    const float* src = blockIdx.y ? text : image;
    __nv_bfloat16* dst = blockIdx.y ? g_txt : g_img;
    int lane = tid & 31, wid = tid >> 5;

    float4 v = ((const float4*)(src + (size_t)row * DIM))[tid];
    float ss = v.x * v.x + v.y * v.y + v.z * v.z + v.w * v.w;
#pragma unroll
    for (int o = 16; o; o >>= 1) ss += __shfl_xor_sync(0xffffffffu, ss, o);
    __shared__ float wss[4];
    if (lane == 0) wss[wid] = ss;
    __syncthreads();
    float tot = wss[0] + wss[1] + wss[2] + wss[3];
    float inv = 1.0f / fmaxf(sqrtf(tot), 1e-12f);

    __nv_bfloat162* dp = (__nv_bfloat162*)(dst + (size_t)row * DIM);
    dp[2 * tid]     = __floats2bfloat162_rn(v.x * inv, v.y * inv);
    dp[2 * tid + 1] = __floats2bfloat162_rn(v.z * inv, v.w * inv);
}

// ---------------------------------------------------------------------------
// Main kernel: single pass over S = img_n @ txt_n^T.
// grid (64, 16), 512 threads (16 warps = 4m x 4n), warp tile 32x64.
// x = 128-row m-block, y = 512-col n-group processed as 2 halves of 256.
// A panel (128x512) resident in smem; B 2-stage cp.async ring (32KB/stage),
// ONE barrier per chunk: top-of-loop sync doubles as overwrite-safety, and
// the next chunk's prefetch is issued before compute so it overlaps fully.
// ---------------------------------------------------------------------------
__global__ __launch_bounds__(512, 1)
void unicl_gemm_kernel(float* __restrict__ out) {
    extern __shared__ char sm[];
    uint32_t sbase = (uint32_t)__cvta_generic_to_shared(sm);
    const uint32_t As_u = sbase;               // [8 k-chunks][128 rows][64 k]
    const uint32_t Bs_u = sbase + 131072u;     // 2 stages x [256 cols][64 k]
    int*   keys_s = (int*)(sm + 196608);       // 512
    float* row_se = (float*)(sm + 198656);     // 128
    float* row_dt = row_se + 128;              // 128
    float* col_se = (float*)(sm + 199680);     // 512
    float* col_dt = col_se + 512;              // 512
    int*   flag_s = (int*)(sm + 203776);
    float* red_s  = (float*)(sm + 203776);     // reused for final reduce (512)

    int tid = threadIdx.x, lane = tid & 31, wid = tid >> 5;
    int gm0 = blockIdx.x * 128;
    int n0  = blockIdx.y * 512;
    const __nv_bfloat16* Ag = g_img;
    const __nv_bfloat16* Bg = g_txt;

    for (int i = tid; i < 128; i += 512) { row_se[i] = 0.0f; row_dt[i] = 0.0f; }
    for (int i = tid; i < 512; i += 512) {
        col_se[i] = 0.0f; col_dt[i] = 0.0f;
        keys_s[i] = g_key[n0 + i];
    }

    // --- A prologue: 128x512 bf16 into [s8][128][64] swizzled ---
#pragma unroll
    for (int q = 0; q < 16; q++) {
        int idx = tid + q * 512;
        int s8 = idx >> 10, row = (idx >> 3) & 127, ch = idx & 7;
        const void* src = Ag + (size_t)(gm0 + row) * DIM + s8 * 64 + ch * 8;
        uint32_t dst = As_u + s8 * 16384 + row * 128 + ((ch ^ (row & 7)) << 4);
        CP_ASYNC16(dst, src);
    }
    CP_COMMIT();

    auto issueB = [&](int gs) {
        int t = gs >> 3, s8 = gs & 7;
        const __nv_bfloat16* bsrc = Bg + (size_t)(n0 + t * 256) * DIM + s8 * 64;
        uint32_t bdst = Bs_u + (uint32_t)(gs & 1) * 32768u;
#pragma unroll
        for (int q = 0; q < 4; q++) {
            int idx = tid + q * 512;
            int row = idx >> 3, ch = idx & 7;
            CP_ASYNC16(bdst + row * 128 + ((ch ^ (row & 7)) << 4),
                       bsrc + (size_t)row * DIM + ch * 8);
        }
    };
    issueB(0); CP_COMMIT();

    // --- warp geometry: 4 m-warps (32 rows) x 4 n-warps (64 cols) ---
    int warp_m = (wid & 3) * 32;
    int warp_n = (wid >> 2) * 64;
    int g = lane >> 2, tig = lane & 3;
    uint32_t a_off = (uint32_t)(warp_m + (lane & 15)) * 128;
    uint32_t hiA = (uint32_t)(lane >> 4);
    uint32_t swA = (uint32_t)(lane & 7);
    int rB0 = warp_n + (lane & 7) + ((lane >> 4) << 3);
    uint32_t b_off = (uint32_t)rB0 * 128;
    uint32_t hiB = (uint32_t)((lane >> 3) & 1);
    uint32_t swB = (uint32_t)(lane & 7);

    int mykey[4];
#pragma unroll
    for (int ri = 0; ri < 4; ri++)
        mykey[ri] = g_key[gm0 + warp_m + g + ri * 8];

    float rse[4] = {0.f, 0.f, 0.f, 0.f};
    float rdt[4] = {0.f, 0.f, 0.f, 0.f};
    const float K2 = SCALE * 1.44269504f;

    for (int t = 0; t < 2; t++) {
        float c[2][8][4];
#pragma unroll
        for (int mf = 0; mf < 2; mf++)
#pragma unroll
            for (int nf = 0; nf < 8; nf++)
#pragma unroll
                for (int e = 0; e < 4; e++) c[mf][nf][e] = 0.0f;

#pragma unroll 1
        for (int s8 = 0; s8 < 8; s8++) {
            int gs = t * 8 + s8;
            // Chunk gs's data is the oldest pending cp.async group.
            CP_WAIT(0);
            __syncthreads();   // also guarantees buffer (gs+1)&1 is reusable
            if (gs + 1 < 16) { issueB(gs + 1); CP_COMMIT(); }

            uint32_t Ab = As_u + s8 * 16384;
            uint32_t Bb = Bs_u + (uint32_t)(gs & 1) * 32768u;
#pragma unroll
            for (int k16 = 0; k16 < 4; k16++) {
                uint32_t a0[4], a1[4], b[4][4];
                uint32_t cA = ((k16 * 2 + hiA) ^ swA) << 4;
                LDSM4(a0, Ab + a_off + cA);
                LDSM4(a1, Ab + a_off + 2048 + cA);
                uint32_t cB = ((k16 * 2 + hiB) ^ swB) << 4;
                LDSM4(b[0], Bb + b_off + cB);
                LDSM4(b[1], Bb + b_off + 2048 + cB);
                LDSM4(b[2], Bb + b_off + 4096 + cB);
                LDSM4(b[3], Bb + b_off + 6144 + cB);
#pragma unroll
                for (int j = 0; j < 4; j++) {
                    MMA_BF16(c[0][2 * j],     a0, b[j][0], b[j][1]);
                    MMA_BF16(c[0][2 * j + 1], a0, b[j][2], b[j][3]);
                    MMA_BF16(c[1][2 * j],     a1, b[j][0], b[j][1]);
                    MMA_BF16(c[1][2 * j + 1], a1, b[j][2], b[j][3]);
                }
            }
        }

        // --- epilogue for n-half t (overlaps next chunk's B load) ---
        float cse[16], cdt[16];
#pragma unroll
        for (int p = 0; p < 16; p++) { cse[p] = 0.0f; cdt[p] = 0.0f; }
        const int* ks = keys_s + t * 256 + warp_n;
#pragma unroll
        for (int mf = 0; mf < 2; mf++) {
#pragma unroll
            for (int nf = 0; nf < 8; nf++) {
#pragma unroll
                for (int e = 0; e < 4; e++) {
                    float cv = c[mf][nf][e];
                    float ex;
                    asm("ex2.approx.ftz.f32 %0, %1;" : "=f"(ex)
                        : "f"(fmaf(cv, K2, -K2)));
                    int ri = mf * 2 + (e >> 1);
                    int p  = nf * 2 + (e & 1);
                    rse[ri] += ex;
                    cse[p]  += ex;
                    int key = ks[nf * 8 + tig * 2 + (e & 1)];
                    if (key == mykey[ri]) { rdt[ri] += cv; cdt[p] += cv; }
                }
            }
        }
#pragma unroll
        for (int p = 0; p < 16; p++) {
            cse[p] += __shfl_xor_sync(0xffffffffu, cse[p], 4);
            cse[p] += __shfl_xor_sync(0xffffffffu, cse[p], 8);
            cse[p] += __shfl_xor_sync(0xffffffffu, cse[p], 16);
            cdt[p] += __shfl_xor_sync(0xffffffffu, cdt[p], 4);
            cdt[p] += __shfl_xor_sync(0xffffffffu, cdt[p], 8);
            cdt[p] += __shfl_xor_sync(0xffffffffu, cdt[p], 16);
        }
#pragma unroll
        for (int q = 0; q < 2; q++) {
            int p = g * 2 + q;
            int cidx = t * 256 + warp_n + (p >> 1) * 8 + tig * 2 + (p & 1);
            atomicAdd(&col_se[cidx], cse[p]);
            atomicAdd(&col_dt[cidx], cdt[p]);
        }
    }

    // --- row reduction + CTA flush ---
#pragma unroll
    for (int ri = 0; ri < 4; ri++) {
        float v = rse[ri];
        v += __shfl_xor_sync(0xffffffffu, v, 1);
        v += __shfl_xor_sync(0xffffffffu, v, 2);
        float w = rdt[ri];
        w += __shfl_xor_sync(0xffffffffu, w, 1);
        w += __shfl_xor_sync(0xffffffffu, w, 2);
        if (tig == 0) {
            atomicAdd(&row_se[warp_m + g + ri * 8], v);
            atomicAdd(&row_dt[warp_m + g + ri * 8], w);
        }
    }
    __syncthreads();
    for (int i = tid; i < 128; i += 512) {
        atomicAdd(&g_rowsum[gm0 + i], row_se[i]);
        atomicAdd(&g_rowdot[gm0 + i], row_dt[i]);
    }
    for (int i = tid; i < 512; i += 512) {
        atomicAdd(&g_colsum[n0 + i], col_se[i]);
        atomicAdd(&g_coldot[n0 + i], col_dt[i]);
    }

    // --- last CTA computes the final loss ---
    __threadfence();
    __syncthreads();
    if (tid == 0) {
        int prev = atomicAdd(&g_done, 1);
        flag_s[0] = (prev == gridDim.x * gridDim.y - 1) ? 1 : 0;
    }
    __syncthreads();
    if (flag_s[0]) {
        __threadfence();
        float s = 0.0f;
        for (int i = tid; i < NROWS; i += 512) {
            float inv = SCALE / g_cnt[i];
            s += 2.0f * SCALE + logf(g_rowsum[i]) + logf(g_colsum[i])
                 - (g_rowdot[i] + g_coldot[i]) * inv;
        }
        __syncthreads();
        red_s[tid] = s;
        __syncthreads();
        for (int o = 256; o; o >>= 1) {
            if (tid < o) red_s[tid] += red_s[tid + o];
            __syncthreads();
        }
        if (tid == 0) out[0] = red_s[0] * (1.0f / (2.0f * NROWS));
    }
}

// ---------------------------------------------------------------------------
extern "C" void kernel_launch(void* const* d_in, const int* in_sizes, int n_in,
                              void* d_out, int out_size) {
    const float* text   = (const float*)d_in[0];
    const float* image  = (const float*)d_in[1];
    const int*   labels = (const int*)d_in[2];
    float* out = (float*)d_out;

    prep_kernel<<<dim3(NROWS + 1, 2), 128>>>(text, image, labels);

    int smem_bytes = 205824;
    cudaFuncSetAttribute(unicl_gemm_kernel,
                         cudaFuncAttributeMaxDynamicSharedMemorySize, smem_bytes);
    unicl_gemm_kernel<<<dim3(64, 16), 512, smem_bytes>>>(out);
}